// round 5
// baseline (speedup 1.0000x reference)
#include <cuda_runtime.h>

#define BB   4
#define CC   128
#define HH   128
#define WW   128
#define NLOW 1024          // 32*32 low-res positions
#define NPLANES (BB * CC)  // 512

// Scratch (no dynamic allocation allowed)
__device__ float4 g_wi[BB * NLOW];   // {w0/16, w1/16, bits(i0), bits(i1)}

// -------------------------------------------------------------------------
// Kernel 1: per-row top-2 over 1024 values + 2-way softmax (/16 folded in).
// One warp per row (B*NLOW = 4096 rows), float4 loads.
// -------------------------------------------------------------------------
__global__ void __launch_bounds__(256) topk_kernel(const float* __restrict__ attn)
{
    int warp = blockIdx.x * 8 + (threadIdx.x >> 5);   // 0..4095
    int lane = threadIdx.x & 31;

    const float4* row = (const float4*)(attn + (size_t)warp * NLOW);

    float v0 = -1e30f, v1 = -1e30f;
    int   i0 = 0,      i1 = 0;

    #pragma unroll
    for (int s = 0; s < 8; s++) {
        int j4 = lane + s * 32;
        float4 x = __ldg(row + j4);
        int base = j4 * 4;
        #pragma unroll
        for (int e = 0; e < 4; e++) {
            float xv = (e == 0) ? x.x : (e == 1) ? x.y : (e == 2) ? x.z : x.w;
            int   xi = base + e;
            if (xv > v0)      { v1 = v0; i1 = i0; v0 = xv; i0 = xi; }
            else if (xv > v1) { v1 = xv; i1 = xi; }
        }
    }

    #pragma unroll
    for (int off = 16; off; off >>= 1) {
        float ov0 = __shfl_xor_sync(0xffffffffu, v0, off);
        int   oi0 = __shfl_xor_sync(0xffffffffu, i0, off);
        float ov1 = __shfl_xor_sync(0xffffffffu, v1, off);
        int   oi1 = __shfl_xor_sync(0xffffffffu, i1, off);
        if (ov0 > v0) {
            if (v0 > ov1) { v1 = v0;  i1 = i0;  }
            else          { v1 = ov1; i1 = oi1; }
            v0 = ov0; i0 = oi0;
        } else if (ov0 > v1) {
            v1 = ov0; i1 = oi0;
        }
    }

    if (lane == 0) {
        float e   = __expf(v1 - v0);                 // <= 1
        float inv = 1.0f / ((1.0f + e) * 16.0f);     // /r2 folded in
        g_wi[warp] = make_float4(inv, e * inv,
                                 __int_as_float(i0), __int_as_float(i1));
    }
}

// -------------------------------------------------------------------------
// Kernel 2: one 512-thread block per (b,c) plane, 4 CTAs/SM -> single wave.
//   Thread t handles low-res positions t and t+512: pools two 4x4 block
//   sums into smem, one barrier, then gathers + broadcast-writes two 4x4
//   output blocks.
// -------------------------------------------------------------------------
__global__ void __launch_bounds__(512, 4) resample_kernel(const float* __restrict__ v,
                                                          float* __restrict__ out)
{
    __shared__ float S[NLOW];

    const int plane = blockIdx.x;        // 0 .. 511
    const int b     = plane >> 7;        // / CC
    const int t     = threadIdx.x;       // 0 .. 511

    const int n0 = t;                    // first low-res position
    const int n1 = t + 512;              // second low-res position

    // addresses of the two 4x4 tiles (n>>5 = block row, n&31 = block col)
    const size_t base = (size_t)plane * (HH * WW);
    const size_t off0 = base + ((n0 >> 5) * 4) * WW + (n0 & 31) * 4;
    const size_t off1 = base + ((n1 >> 5) * 4) * WW + (n1 & 31) * 4;

    // Prefetch both weight vectors (independent of pooling)
    float4 wiA = __ldg(&g_wi[b * NLOW + n0]);
    float4 wiB = __ldg(&g_wi[b * NLOW + n1]);

    // Pool first 4x4 block (4 independent LDG.128, coalesced per warp)
    {
        const float* p = v + off0;
        float4 r0 = __ldg((const float4*)(p));
        float4 r1 = __ldg((const float4*)(p + WW));
        float4 r2 = __ldg((const float4*)(p + 2 * WW));
        float4 r3 = __ldg((const float4*)(p + 3 * WW));
        S[n0] = (r0.x + r0.y + r0.z + r0.w)
              + (r1.x + r1.y + r1.z + r1.w)
              + (r2.x + r2.y + r2.z + r2.w)
              + (r3.x + r3.y + r3.z + r3.w);
    }
    // Pool second 4x4 block
    {
        const float* p = v + off1;
        float4 r0 = __ldg((const float4*)(p));
        float4 r1 = __ldg((const float4*)(p + WW));
        float4 r2 = __ldg((const float4*)(p + 2 * WW));
        float4 r3 = __ldg((const float4*)(p + 3 * WW));
        S[n1] = (r0.x + r0.y + r0.z + r0.w)
              + (r1.x + r1.y + r1.z + r1.w)
              + (r2.x + r2.y + r2.z + r2.w)
              + (r3.x + r3.y + r3.z + r3.w);
    }

    __syncthreads();

    // Gather + broadcast write, position n0
    {
        float val = fmaf(wiA.x, S[__float_as_int(wiA.z)],
                         wiA.y * S[__float_as_int(wiA.w)]);
        float4 vv = make_float4(val, val, val, val);
        float* q = out + off0;
        *(float4*)(q)          = vv;
        *(float4*)(q + WW)     = vv;
        *(float4*)(q + 2 * WW) = vv;
        *(float4*)(q + 3 * WW) = vv;
    }
    // Gather + broadcast write, position n1
    {
        float val = fmaf(wiB.x, S[__float_as_int(wiB.z)],
                         wiB.y * S[__float_as_int(wiB.w)]);
        float4 vv = make_float4(val, val, val, val);
        float* q = out + off1;
        *(float4*)(q)          = vv;
        *(float4*)(q + WW)     = vv;
        *(float4*)(q + 2 * WW) = vv;
        *(float4*)(q + 3 * WW) = vv;
    }
}

extern "C" void kernel_launch(void* const* d_in, const int* in_sizes, int n_in,
                              void* d_out, int out_size)
{
    const float* v_high = (const float*)d_in[0];   // (4,128,128,128)
    const float* attn   = (const float*)d_in[1];   // (4,1024,1024)
    float* out          = (float*)d_out;           // (4,128,128,128)

    topk_kernel<<<512, 256>>>(attn);               // 4096 rows, 1 warp each
    resample_kernel<<<NPLANES, 512>>>(v_high, out);
}